// round 7
// baseline (speedup 1.0000x reference)
#include <cuda_runtime.h>
#include <cuda_bf16.h>
#include <cstdint>

#define HID    1024
#define BATCH  32
#define LAYERS 3
#define OUTDIM 2500
#define GRID_N 50
#define MODES  32
#define TIME   64

#define GRU_MT  192         // 3072/16 m-tiles per matrix
#define KT16    64          // 1024/16 k16-tiles
#define KS8     8           // K-slices per matrix (K=128 each)
#define FC_MT   160         // padded 2560/16
#define FC_KT16 64
#define KS_FC   16
#define KSLICE_FC 64
#define M_FC_PAD 2512

// ---------------- persistent device state ------------------------------------
__device__ float g_h[2][LAYERS][BATCH][HID];
__device__ float g_x[BATCH][HID];
__device__ float g_ct[MODES][GRID_N];
__device__ float g_st[MODES][GRID_N];
__device__ float g_part6[6 * KS8 * 3072 * 32];        // GRU split-K partials
__device__ float g_fpart[KS_FC * 32 * M_FC_PAD];      // FC partials

// split-bf16 weights, fragment order. Per 16x16 tile: 128 uint32 hi, 128 uint32 lo.
// mats 0..2 = W_ih l0..2, 3..5 = W_hh l0..2.
__device__ uint32_t g_W32[(size_t)6 * GRU_MT * KT16 * 256];   // 75.5 MB
__device__ uint32_t g_F32[(size_t)FC_MT * FC_KT16 * 256];     // 10.5 MB

// ---------------- helpers ----------------------------------------------------
__device__ __forceinline__ uint32_t pack_bf2(float a, float b) {
    __nv_bfloat162 v;
    v.x = __float2bfloat16_rn(a);
    v.y = __float2bfloat16_rn(b);
    return *reinterpret_cast<uint32_t*>(&v);
}

__device__ __forceinline__ void mma16(float* c,
                                      uint32_t a0, uint32_t a1, uint32_t a2, uint32_t a3,
                                      uint32_t b0, uint32_t b1) {
    asm volatile(
        "mma.sync.aligned.m16n8k16.row.col.f32.bf16.bf16.f32 "
        "{%0,%1,%2,%3}, {%4,%5,%6,%7}, {%8,%9}, {%0,%1,%2,%3};"
        : "+f"(c[0]), "+f"(c[1]), "+f"(c[2]), "+f"(c[3])
        : "r"(a0), "r"(a1), "r"(a2), "r"(a3), "r"(b0), "r"(b1));
}

// ---------------- init -------------------------------------------------------
__global__ void init_kernel(const float* __restrict__ x)
{
    int tid    = blockIdx.x * blockDim.x + threadIdx.x;
    int stride = gridDim.x * blockDim.x;

    float* hflat = (float*)g_h;
    for (int i = tid; i < 2 * LAYERS * BATCH * HID; i += stride) hflat[i] = 0.0f;

    float* xflat = (float*)g_x;
    for (int i = tid; i < BATCH * HID; i += stride) xflat[i] = x[i];

    for (int i = tid; i < MODES * GRID_N; i += stride) {
        int t = i / GRID_N;
        int n = i % GRID_N;
        float arg = 2.0f * (float)(t - 16) * (float)n / 50.0f;  // units of pi
        g_ct[t][n] = cospif(arg);
        g_st[t][n] = sinpif(arg);
    }
}

// ---------------- weight repack: fp32 -> split-bf16 fragment order -----------
// idx decodes: [mat][mt][kt][half(hi/lo)][lane][j], 256 uint32 per tile.
// frag j of lane (g,t): j0=(g, 2t..), j1=(g+8, 2t..), j2=(g, 2t+8..), j3=(g+8, 2t+8..)
__global__ void repack_gru(const float* __restrict__ W_ih,
                           const float* __restrict__ W_hh)
{
    int64_t total = (int64_t)6 * GRU_MT * KT16 * 256;
    for (int64_t idx = (int64_t)blockIdx.x * blockDim.x + threadIdx.x;
         idx < total; idx += (int64_t)gridDim.x * blockDim.x) {
        int w      = (int)(idx & 255);
        int half   = w >> 7;            // 0 = hi, 1 = lo
        int within = w & 127;
        int lane   = within >> 2;
        int j      = within & 3;
        int kt     = (int)((idx >> 8) & (KT16 - 1));
        int tmp    = (int)(idx >> 14);  // mat*GRU_MT + mt
        int mt     = tmp % GRU_MT;
        int mat    = tmp / GRU_MT;
        int l      = mat % 3;
        const float* src = ((mat < 3) ? W_ih : W_hh) + (size_t)l * 3 * HID * HID;
        int g = lane >> 2, t = lane & 3;
        int r = mt * 16 + g + (j & 1) * 8;
        int c = kt * 16 + 2 * t + (j >> 1) * 8;
        float f0 = src[(size_t)r * HID + c];
        float f1 = src[(size_t)r * HID + c + 1];
        if (half == 0) {
            g_W32[idx] = pack_bf2(f0, f1);
        } else {
            float h0 = __bfloat162float(__float2bfloat16_rn(f0));
            float h1 = __bfloat162float(__float2bfloat16_rn(f1));
            g_W32[idx] = pack_bf2(f0 - h0, f1 - h1);
        }
    }
}

__global__ void repack_fc(const float* __restrict__ fc_w)
{
    int64_t total = (int64_t)FC_MT * FC_KT16 * 256;
    for (int64_t idx = (int64_t)blockIdx.x * blockDim.x + threadIdx.x;
         idx < total; idx += (int64_t)gridDim.x * blockDim.x) {
        int w      = (int)(idx & 255);
        int half   = w >> 7;
        int within = w & 127;
        int lane   = within >> 2;
        int j      = within & 3;
        int kt     = (int)((idx >> 8) & (FC_KT16 - 1));
        int mt     = (int)(idx >> 14);
        int g = lane >> 2, t = lane & 3;
        int r = mt * 16 + g + (j & 1) * 8;
        int c = kt * 16 + 2 * t + (j >> 1) * 8;
        float f0 = (r < OUTDIM) ? fc_w[(size_t)r * HID + c]     : 0.0f;
        float f1 = (r < OUTDIM) ? fc_w[(size_t)r * HID + c + 1] : 0.0f;
        if (half == 0) {
            g_F32[idx] = pack_bf2(f0, f1);
        } else {
            float h0 = __bfloat162float(__float2bfloat16_rn(f0));
            float h1 = __bfloat162float(__float2bfloat16_rn(f1));
            g_F32[idx] = pack_bf2(f0 - h0, f1 - h1);
        }
    }
}

// ---------------- GRU gate GEMM (split-K, 3-term split-bf16) -----------------
// grid (48, 8, njobs): x = m-block (64 rows), y = K-slice (K=128), z = job.
// Partials -> g_part6[(mat*8+ks)*3072 + m]*32 + n.
__global__ __launch_bounds__(128) void gru_gemm(
    int src, int j0, int j1, int j2, int j3)
{
    __shared__ uint32_t sbh[BATCH][68];   // stride 68: banks 4g+t, conflict-free
    __shared__ uint32_t sbl[BATCH][68];

    const int mat  = (blockIdx.z == 0) ? j0 : (blockIdx.z == 1) ? j1
                   : (blockIdx.z == 2) ? j2 : j3;
    const int ks   = blockIdx.y;
    const int warp = threadIdx.x >> 5;
    const int lane = threadIdx.x & 31;
    const int g    = lane >> 2;
    const int t    = lane & 3;
    const int m0   = blockIdx.x * 64 + warp * 16;
    const int koff = ks * 128;
    const int l    = mat % 3;

    const float* bsrc = (mat >= 3) ? &g_h[src][l][0][0]
                      : (l == 0)   ? &g_x[0][0]
                                   : &g_h[src ^ 1][l - 1][0][0];

    // stage B: split into hi/lo bf16 pairs (packed per 2 k-values)
    for (int i = threadIdx.x; i < BATCH * 64; i += 128) {
        int n  = i >> 6;
        int kp = i & 63;
        float f0 = bsrc[n * HID + koff + kp * 2];
        float f1 = bsrc[n * HID + koff + kp * 2 + 1];
        float h0 = __bfloat162float(__float2bfloat16_rn(f0));
        float h1 = __bfloat162float(__float2bfloat16_rn(f1));
        sbh[n][kp] = pack_bf2(f0, f1);
        sbl[n][kp] = pack_bf2(f0 - h0, f1 - h1);
    }
    __syncthreads();

    // A: coalesced uint4 fragments (hi first 32 uint4 of tile, lo next 32)
    const int mt = blockIdx.x * 4 + warp;
    const uint4* pT = (const uint4*)(g_W32
                   + (((size_t)mat * GRU_MT + mt) * KT16 + ks * 8) * 256);

    float c[4][4] = {};

    #pragma unroll
    for (int kt = 0; kt < 8; kt++) {
        uint4 ah = pT[kt * 64 + lane];
        uint4 al = pT[kt * 64 + 32 + lane];
        int kp0 = kt * 8 + t;

        #pragma unroll
        for (int nt = 0; nt < 4; nt++) {
            int n = nt * 8 + g;
            uint32_t bh0 = sbh[n][kp0], bh1 = sbh[n][kp0 + 4];
            uint32_t bl0 = sbl[n][kp0], bl1 = sbl[n][kp0 + 4];
            mma16(c[nt], ah.x, ah.y, ah.z, ah.w, bh0, bh1);
            mma16(c[nt], ah.x, ah.y, ah.z, ah.w, bl0, bl1);
            mma16(c[nt], al.x, al.y, al.z, al.w, bh0, bh1);
        }
    }

    #pragma unroll
    for (int nt = 0; nt < 4; nt++) {
        int n = nt * 8 + 2 * t;
        float* base = g_part6 + (((size_t)mat * KS8 + ks) * 3072 + (m0 + g)) * 32 + n;
        *(float2*)base            = make_float2(c[nt][0], c[nt][1]);
        *(float2*)(base + 8 * 32) = make_float2(c[nt][2], c[nt][3]);
    }
}

// ---------------- GRU cell pointwise -----------------------------------------
__global__ __launch_bounds__(256) void gru_cell(
    int layer, int src,
    const float* __restrict__ b_ih_all,
    const float* __restrict__ b_hh_all)
{
    const int dst = src ^ 1;
    const int gid = blockIdx.x * 256 + threadIdx.x;
    const int b   = gid & 31;
    const int u   = gid >> 5;

    float i_r = 0.f, i_z = 0.f, i_n = 0.f, h_r = 0.f, h_z = 0.f, h_n = 0.f;
    #pragma unroll
    for (int ks = 0; ks < KS8; ks++) {
        const float* p = g_part6 + ((size_t)layer * KS8 + ks) * 3072 * 32;
        i_r += p[(u)        * 32 + b];
        i_z += p[(u + 1024) * 32 + b];
        i_n += p[(u + 2048) * 32 + b];
    }
    #pragma unroll
    for (int ks = 0; ks < KS8; ks++) {
        const float* p = g_part6 + ((size_t)(3 + layer) * KS8 + ks) * 3072 * 32;
        h_r += p[(u)        * 32 + b];
        h_z += p[(u + 1024) * 32 + b];
        h_n += p[(u + 2048) * 32 + b];
    }

    const float* bih = b_ih_all + layer * 3 * HID;
    const float* bhh = b_hh_all + layer * 3 * HID;
    i_r += bih[u];           h_r += bhh[u];
    i_z += bih[u + HID];     h_z += bhh[u + HID];
    i_n += bih[u + 2 * HID]; h_n += bhh[u + 2 * HID];

    float r = 1.0f / (1.0f + expf(-(i_r + h_r)));
    float z = 1.0f / (1.0f + expf(-(i_z + h_z)));
    float n = tanhf(i_n + r * h_n);

    float h_old = g_h[src][layer][b][u];
    g_h[dst][layer][b][u] = (1.0f - z) * n + z * h_old;
}

// ---------------- FC GEMM (split-K, 3-term split-bf16) -----------------------
// grid (40, 16). Partials -> g_fpart[(ks*32+n)*M_FC_PAD + m].
__global__ __launch_bounds__(128) void fc_gemm(int src)
{
    __shared__ uint32_t sbh[BATCH][36];   // 32 pairs + 4 pad, banks 4g+t
    __shared__ uint32_t sbl[BATCH][36];

    const int dst  = src ^ 1;
    const int ks   = blockIdx.y;
    const int warp = threadIdx.x >> 5;
    const int lane = threadIdx.x & 31;
    const int g    = lane >> 2;
    const int t    = lane & 3;
    const int m0   = blockIdx.x * 64 + warp * 16;
    const int koff = ks * KSLICE_FC;

    const float* bsrc = &g_h[dst][LAYERS - 1][0][0];
    for (int i = threadIdx.x; i < BATCH * 32; i += 128) {
        int n  = i >> 5;
        int kp = i & 31;
        float f0 = bsrc[n * HID + koff + kp * 2];
        float f1 = bsrc[n * HID + koff + kp * 2 + 1];
        float h0 = __bfloat162float(__float2bfloat16_rn(f0));
        float h1 = __bfloat162float(__float2bfloat16_rn(f1));
        sbh[n][kp] = pack_bf2(f0, f1);
        sbl[n][kp] = pack_bf2(f0 - h0, f1 - h1);
    }
    __syncthreads();

    const int mt = blockIdx.x * 4 + warp;
    const uint4* pT = (const uint4*)(g_F32
                   + (((size_t)mt) * FC_KT16 + ks * 4) * 256);

    float c[4][4] = {};

    #pragma unroll
    for (int kt = 0; kt < 4; kt++) {
        uint4 ah = pT[kt * 64 + lane];
        uint4 al = pT[kt * 64 + 32 + lane];
        int kp0 = kt * 8 + t;

        #pragma unroll
        for (int nt = 0; nt < 4; nt++) {
            int n = nt * 8 + g;
            uint32_t bh0 = sbh[n][kp0], bh1 = sbh[n][kp0 + 4];
            uint32_t bl0 = sbl[n][kp0], bl1 = sbl[n][kp0 + 4];
            mma16(c[nt], ah.x, ah.y, ah.z, ah.w, bh0, bh1);
            mma16(c[nt], ah.x, ah.y, ah.z, ah.w, bl0, bl1);
            mma16(c[nt], al.x, al.y, al.z, al.w, bh0, bh1);
        }
    }

    #pragma unroll
    for (int nt = 0; nt < 4; nt++) {
        #pragma unroll
        for (int j = 0; j < 4; j++) {
            int n = nt * 8 + 2 * t + (j & 1);
            int m = m0 + g + ((j >> 1) * 8);
            if (m < OUTDIM)
                g_fpart[((size_t)ks * 32 + n) * M_FC_PAD + m] = c[nt][j];
        }
    }
}

// ---------------- spectral crop: FC reduce+bias, DFT, feedback ---------------
__global__ __launch_bounds__(256) void spectral_kernel(
    const float* __restrict__ fc_b, float* __restrict__ outp)
{
    const int b = blockIdx.x;
    __shared__ float a[OUTDIM];
    __shared__ float cre[GRID_N * MODES];
    __shared__ float cim[GRID_N * MODES];

    for (int i = threadIdx.x; i < OUTDIM; i += blockDim.x) {
        float s = fc_b[i];
        #pragma unroll
        for (int ks = 0; ks < KS_FC; ks++)
            s += g_fpart[((size_t)ks * 32 + b) * M_FC_PAD + i];
        a[i] = s;
        outp[b * OUTDIM + i] = s;
    }
    __syncthreads();

    for (int i = threadIdx.x; i < GRID_N * MODES; i += blockDim.x) {
        int m = i / MODES;
        int q = i % MODES;
        float sre = 0.f, sim = 0.f;
        #pragma unroll 5
        for (int n = 0; n < GRID_N; n++) {
            float v = a[m * GRID_N + n];
            sre += v * g_ct[q][n];
            sim -= v * g_st[q][n];
        }
        cre[m * MODES + q] = sre;
        cim[m * MODES + q] = sim;
    }
    __syncthreads();

    for (int i = threadIdx.x; i < MODES * MODES; i += blockDim.x) {
        int p = i / MODES;
        int q = i % MODES;
        float s = 0.f;
        #pragma unroll 5
        for (int m = 0; m < GRID_N; m++)
            s += g_ct[p][m] * cre[m * MODES + q] + g_st[p][m] * cim[m * MODES + q];
        g_x[b][i] = s;
    }
}

// ---------------- driver -----------------------------------------------------
extern "C" void kernel_launch(void* const* d_in, const int* in_sizes, int n_in,
                              void* d_out, int out_size)
{
    const float* x     = (const float*)d_in[0];
    const float* W_ih  = (const float*)d_in[1];
    const float* W_hh  = (const float*)d_in[2];
    const float* b_ih  = (const float*)d_in[3];
    const float* b_hh  = (const float*)d_in[4];
    const float* fc_w  = (const float*)d_in[5];
    const float* fc_b  = (const float*)d_in[6];
    float*       out   = (float*)d_out;

    init_kernel<<<64, 256>>>(x);
    repack_gru<<<592, 256>>>(W_ih, W_hh);
    repack_fc<<<128, 256>>>(fc_w);

    for (int t = 0; t < TIME; t++) {
        int src = t & 1;
        float* outp = out + (size_t)t * BATCH * OUTDIM;

        // K1: all hh mats (depend only on old h) + ih layer 0 — one fat launch
        gru_gemm<<<dim3(48, 8, 4), 128>>>(src, 0, 3, 4, 5);
        gru_cell<<<128, 256>>>(0, src, b_ih, b_hh);
        gru_gemm<<<dim3(48, 8, 1), 128>>>(src, 1, 0, 0, 0);
        gru_cell<<<128, 256>>>(1, src, b_ih, b_hh);
        gru_gemm<<<dim3(48, 8, 1), 128>>>(src, 2, 0, 0, 0);
        gru_cell<<<128, 256>>>(2, src, b_ih, b_hh);
        fc_gemm<<<dim3(40, KS_FC), 128>>>(src);
        spectral_kernel<<<BATCH, 256>>>(fc_b, outp);
    }
}

// round 8
// speedup vs baseline: 1.0539x; 1.0539x over previous
#include <cuda_runtime.h>
#include <cuda_bf16.h>
#include <cstdint>

#define HID    1024
#define BATCH  32
#define LAYERS 3
#define OUTDIM 2500
#define GRID_N 50
#define MODES  32
#define TIME   64

#define GRU_MT  192         // 3072/16 m-tiles per matrix
#define KT16    64          // 1024/16 k16-tiles
#define KS8     8           // K-slices per matrix (K=128 each)
#define FC_MT   160         // padded 2560/16
#define FC_KT16 64
#define KS_FC   16
#define KSLICE_FC 64
#define M_FC_PAD 2512

// ---------------- persistent device state ------------------------------------
__device__ float g_h[2][LAYERS][BATCH][HID];
__device__ float g_x[BATCH][HID];
__device__ float g_ct[MODES][GRID_N];
__device__ float g_st[MODES][GRID_N];
__device__ float g_part6[6 * KS8 * 3072 * 32];        // GRU split-K partials
__device__ float g_fpart[KS_FC * 32 * M_FC_PAD];      // FC partials

// split-bf16 weights, fragment order. Per 16x16 tile: 128 uint32 hi, 128 uint32 lo.
// mats 0..2 = W_ih l0..2, 3..5 = W_hh l0..2.
__device__ uint32_t g_W32[(size_t)6 * GRU_MT * KT16 * 256];   // 75.5 MB
__device__ uint32_t g_F32[(size_t)FC_MT * FC_KT16 * 256];     // 10.5 MB

// ---------------- helpers ----------------------------------------------------
__device__ __forceinline__ uint32_t pack_bf2(float a, float b) {
    __nv_bfloat162 v;
    v.x = __float2bfloat16_rn(a);
    v.y = __float2bfloat16_rn(b);
    return *reinterpret_cast<uint32_t*>(&v);
}

__device__ __forceinline__ void mma16(float* c,
                                      uint32_t a0, uint32_t a1, uint32_t a2, uint32_t a3,
                                      uint32_t b0, uint32_t b1) {
    asm volatile(
        "mma.sync.aligned.m16n8k16.row.col.f32.bf16.bf16.f32 "
        "{%0,%1,%2,%3}, {%4,%5,%6,%7}, {%8,%9}, {%0,%1,%2,%3};"
        : "+f"(c[0]), "+f"(c[1]), "+f"(c[2]), "+f"(c[3])
        : "r"(a0), "r"(a1), "r"(a2), "r"(a3), "r"(b0), "r"(b1));
}

// ---------------- init -------------------------------------------------------
__global__ void init_kernel(const float* __restrict__ x)
{
    int tid    = blockIdx.x * blockDim.x + threadIdx.x;
    int stride = gridDim.x * blockDim.x;

    float* hflat = (float*)g_h;
    for (int i = tid; i < 2 * LAYERS * BATCH * HID; i += stride) hflat[i] = 0.0f;

    float* xflat = (float*)g_x;
    for (int i = tid; i < BATCH * HID; i += stride) xflat[i] = x[i];

    for (int i = tid; i < MODES * GRID_N; i += stride) {
        int t = i / GRID_N;
        int n = i % GRID_N;
        float arg = 2.0f * (float)(t - 16) * (float)n / 50.0f;  // units of pi
        g_ct[t][n] = cospif(arg);
        g_st[t][n] = sinpif(arg);
    }
}

// ---------------- weight repack: fp32 -> split-bf16 fragment order -----------
// idx decodes: [mat][mt][kt][half(hi/lo)][lane][j], 256 uint32 per tile.
// frag j of lane (g,t): j0=(g, 2t..), j1=(g+8, 2t..), j2=(g, 2t+8..), j3=(g+8, 2t+8..)
__global__ void repack_gru(const float* __restrict__ W_ih,
                           const float* __restrict__ W_hh)
{
    int64_t total = (int64_t)6 * GRU_MT * KT16 * 256;
    for (int64_t idx = (int64_t)blockIdx.x * blockDim.x + threadIdx.x;
         idx < total; idx += (int64_t)gridDim.x * blockDim.x) {
        int w      = (int)(idx & 255);
        int half   = w >> 7;            // 0 = hi, 1 = lo
        int within = w & 127;
        int lane   = within >> 2;
        int j      = within & 3;
        int kt     = (int)((idx >> 8) & (KT16 - 1));
        int tmp    = (int)(idx >> 14);  // mat*GRU_MT + mt
        int mt     = tmp % GRU_MT;
        int mat    = tmp / GRU_MT;
        int l      = mat % 3;
        const float* src = ((mat < 3) ? W_ih : W_hh) + (size_t)l * 3 * HID * HID;
        int g = lane >> 2, t = lane & 3;
        int r = mt * 16 + g + (j & 1) * 8;
        int c = kt * 16 + 2 * t + (j >> 1) * 8;
        float f0 = src[(size_t)r * HID + c];
        float f1 = src[(size_t)r * HID + c + 1];
        if (half == 0) {
            g_W32[idx] = pack_bf2(f0, f1);
        } else {
            float h0 = __bfloat162float(__float2bfloat16_rn(f0));
            float h1 = __bfloat162float(__float2bfloat16_rn(f1));
            g_W32[idx] = pack_bf2(f0 - h0, f1 - h1);
        }
    }
}

__global__ void repack_fc(const float* __restrict__ fc_w)
{
    int64_t total = (int64_t)FC_MT * FC_KT16 * 256;
    for (int64_t idx = (int64_t)blockIdx.x * blockDim.x + threadIdx.x;
         idx < total; idx += (int64_t)gridDim.x * blockDim.x) {
        int w      = (int)(idx & 255);
        int half   = w >> 7;
        int within = w & 127;
        int lane   = within >> 2;
        int j      = within & 3;
        int kt     = (int)((idx >> 8) & (FC_KT16 - 1));
        int mt     = (int)(idx >> 14);
        int g = lane >> 2, t = lane & 3;
        int r = mt * 16 + g + (j & 1) * 8;
        int c = kt * 16 + 2 * t + (j >> 1) * 8;
        float f0 = (r < OUTDIM) ? fc_w[(size_t)r * HID + c]     : 0.0f;
        float f1 = (r < OUTDIM) ? fc_w[(size_t)r * HID + c + 1] : 0.0f;
        if (half == 0) {
            g_F32[idx] = pack_bf2(f0, f1);
        } else {
            float h0 = __bfloat162float(__float2bfloat16_rn(f0));
            float h1 = __bfloat162float(__float2bfloat16_rn(f1));
            g_F32[idx] = pack_bf2(f0 - h0, f1 - h1);
        }
    }
}

// ---------------- GRU gate GEMM (split-K, 4-term split-bf16) -----------------
// grid (48, 8, njobs): x = m-block (64 rows), y = K-slice (K=128), z = job.
// Whole A-slice prefetched into registers (16 LDG.128 in flight per lane).
__global__ __launch_bounds__(128) void gru_gemm(
    int src, int j0, int j1, int j2, int j3)
{
    __shared__ uint32_t sbh[BATCH][68];   // stride 68: banks 4g+t, conflict-free
    __shared__ uint32_t sbl[BATCH][68];

    const int mat  = (blockIdx.z == 0) ? j0 : (blockIdx.z == 1) ? j1
                   : (blockIdx.z == 2) ? j2 : j3;
    const int ks   = blockIdx.y;
    const int warp = threadIdx.x >> 5;
    const int lane = threadIdx.x & 31;
    const int g    = lane >> 2;
    const int t    = lane & 3;
    const int m0   = blockIdx.x * 64 + warp * 16;
    const int koff = ks * 128;
    const int l    = mat % 3;

    // issue all A loads first: 16 independent LDG.128 per lane
    const int mt = blockIdx.x * 4 + warp;
    const uint4* pT = (const uint4*)(g_W32
                   + (((size_t)mat * GRU_MT + mt) * KT16 + ks * 8) * 256);
    uint4 ah[8], al[8];
    #pragma unroll
    for (int kt = 0; kt < 8; kt++) ah[kt] = pT[kt * 64 + lane];
    #pragma unroll
    for (int kt = 0; kt < 8; kt++) al[kt] = pT[kt * 64 + 32 + lane];

    const float* bsrc = (mat >= 3) ? &g_h[src][l][0][0]
                      : (l == 0)   ? &g_x[0][0]
                                   : &g_h[src ^ 1][l - 1][0][0];

    // stage B: split into hi/lo bf16 pairs (packed per 2 k-values)
    for (int i = threadIdx.x; i < BATCH * 64; i += 128) {
        int n  = i >> 6;
        int kp = i & 63;
        float f0 = bsrc[n * HID + koff + kp * 2];
        float f1 = bsrc[n * HID + koff + kp * 2 + 1];
        float h0 = __bfloat162float(__float2bfloat16_rn(f0));
        float h1 = __bfloat162float(__float2bfloat16_rn(f1));
        sbh[n][kp] = pack_bf2(f0, f1);
        sbl[n][kp] = pack_bf2(f0 - h0, f1 - h1);
    }
    __syncthreads();

    float c[4][4] = {};

    #pragma unroll
    for (int kt = 0; kt < 8; kt++) {
        int kp0 = kt * 8 + t;
        #pragma unroll
        for (int nt = 0; nt < 4; nt++) {
            int n = nt * 8 + g;
            uint32_t bh0 = sbh[n][kp0], bh1 = sbh[n][kp0 + 4];
            uint32_t bl0 = sbl[n][kp0], bl1 = sbl[n][kp0 + 4];
            mma16(c[nt], ah[kt].x, ah[kt].y, ah[kt].z, ah[kt].w, bh0, bh1);
            mma16(c[nt], ah[kt].x, ah[kt].y, ah[kt].z, ah[kt].w, bl0, bl1);
            mma16(c[nt], al[kt].x, al[kt].y, al[kt].z, al[kt].w, bh0, bh1);
            mma16(c[nt], al[kt].x, al[kt].y, al[kt].z, al[kt].w, bl0, bl1);
        }
    }

    #pragma unroll
    for (int nt = 0; nt < 4; nt++) {
        int n = nt * 8 + 2 * t;
        float* base = g_part6 + (((size_t)mat * KS8 + ks) * 3072 + (m0 + g)) * 32 + n;
        *(float2*)base            = make_float2(c[nt][0], c[nt][1]);
        *(float2*)(base + 8 * 32) = make_float2(c[nt][2], c[nt][3]);
    }
}

// ---------------- GRU cell pointwise -----------------------------------------
__global__ __launch_bounds__(256) void gru_cell(
    int layer, int src,
    const float* __restrict__ b_ih_all,
    const float* __restrict__ b_hh_all)
{
    const int dst = src ^ 1;
    const int gid = blockIdx.x * 256 + threadIdx.x;
    const int b   = gid & 31;
    const int u   = gid >> 5;

    float i_r = 0.f, i_z = 0.f, i_n = 0.f, h_r = 0.f, h_z = 0.f, h_n = 0.f;
    #pragma unroll
    for (int ks = 0; ks < KS8; ks++) {
        const float* p = g_part6 + ((size_t)layer * KS8 + ks) * 3072 * 32;
        i_r += p[(u)        * 32 + b];
        i_z += p[(u + 1024) * 32 + b];
        i_n += p[(u + 2048) * 32 + b];
    }
    #pragma unroll
    for (int ks = 0; ks < KS8; ks++) {
        const float* p = g_part6 + ((size_t)(3 + layer) * KS8 + ks) * 3072 * 32;
        h_r += p[(u)        * 32 + b];
        h_z += p[(u + 1024) * 32 + b];
        h_n += p[(u + 2048) * 32 + b];
    }

    const float* bih = b_ih_all + layer * 3 * HID;
    const float* bhh = b_hh_all + layer * 3 * HID;
    i_r += bih[u];           h_r += bhh[u];
    i_z += bih[u + HID];     h_z += bhh[u + HID];
    i_n += bih[u + 2 * HID]; h_n += bhh[u + 2 * HID];

    float r = 1.0f / (1.0f + expf(-(i_r + h_r)));
    float z = 1.0f / (1.0f + expf(-(i_z + h_z)));
    float n = tanhf(i_n + r * h_n);

    float h_old = g_h[src][layer][b][u];
    g_h[dst][layer][b][u] = (1.0f - z) * n + z * h_old;
}

// ---------------- FC GEMM (split-K, 4-term split-bf16) -----------------------
// grid (40, 16). Partials -> g_fpart[(ks*32+n)*M_FC_PAD + m].
__global__ __launch_bounds__(128) void fc_gemm(int src)
{
    __shared__ uint32_t sbh[BATCH][36];   // 32 pairs + 4 pad
    __shared__ uint32_t sbl[BATCH][36];

    const int dst  = src ^ 1;
    const int ks   = blockIdx.y;
    const int warp = threadIdx.x >> 5;
    const int lane = threadIdx.x & 31;
    const int g    = lane >> 2;
    const int t    = lane & 3;
    const int m0   = blockIdx.x * 64 + warp * 16;
    const int koff = ks * KSLICE_FC;

    // prefetch A fragments: 8 LDG.128 in flight per lane
    const int mt = blockIdx.x * 4 + warp;
    const uint4* pT = (const uint4*)(g_F32
                   + (((size_t)mt) * FC_KT16 + ks * 4) * 256);
    uint4 ah[4], al[4];
    #pragma unroll
    for (int kt = 0; kt < 4; kt++) ah[kt] = pT[kt * 64 + lane];
    #pragma unroll
    for (int kt = 0; kt < 4; kt++) al[kt] = pT[kt * 64 + 32 + lane];

    const float* bsrc = &g_h[dst][LAYERS - 1][0][0];
    for (int i = threadIdx.x; i < BATCH * 32; i += 128) {
        int n  = i >> 5;
        int kp = i & 31;
        float f0 = bsrc[n * HID + koff + kp * 2];
        float f1 = bsrc[n * HID + koff + kp * 2 + 1];
        float h0 = __bfloat162float(__float2bfloat16_rn(f0));
        float h1 = __bfloat162float(__float2bfloat16_rn(f1));
        sbh[n][kp] = pack_bf2(f0, f1);
        sbl[n][kp] = pack_bf2(f0 - h0, f1 - h1);
    }
    __syncthreads();

    float c[4][4] = {};

    #pragma unroll
    for (int kt = 0; kt < 4; kt++) {
        int kp0 = kt * 8 + t;
        #pragma unroll
        for (int nt = 0; nt < 4; nt++) {
            int n = nt * 8 + g;
            uint32_t bh0 = sbh[n][kp0], bh1 = sbh[n][kp0 + 4];
            uint32_t bl0 = sbl[n][kp0], bl1 = sbl[n][kp0 + 4];
            mma16(c[nt], ah[kt].x, ah[kt].y, ah[kt].z, ah[kt].w, bh0, bh1);
            mma16(c[nt], ah[kt].x, ah[kt].y, ah[kt].z, ah[kt].w, bl0, bl1);
            mma16(c[nt], al[kt].x, al[kt].y, al[kt].z, al[kt].w, bh0, bh1);
            mma16(c[nt], al[kt].x, al[kt].y, al[kt].z, al[kt].w, bl0, bl1);
        }
    }

    #pragma unroll
    for (int nt = 0; nt < 4; nt++) {
        #pragma unroll
        for (int j = 0; j < 4; j++) {
            int n = nt * 8 + 2 * t + (j & 1);
            int m = m0 + g + ((j >> 1) * 8);
            if (m < OUTDIM)
                g_fpart[((size_t)ks * 32 + n) * M_FC_PAD + m] = c[nt][j];
        }
    }
}

// ---------------- spectral crop: FC reduce+bias, DFT, feedback ---------------
__global__ __launch_bounds__(256) void spectral_kernel(
    const float* __restrict__ fc_b, float* __restrict__ outp)
{
    const int b = blockIdx.x;
    __shared__ float a[OUTDIM];
    __shared__ float cre[GRID_N * MODES];
    __shared__ float cim[GRID_N * MODES];

    for (int i = threadIdx.x; i < OUTDIM; i += blockDim.x) {
        float s = fc_b[i];
        #pragma unroll
        for (int ks = 0; ks < KS_FC; ks++)
            s += g_fpart[((size_t)ks * 32 + b) * M_FC_PAD + i];
        a[i] = s;
        outp[b * OUTDIM + i] = s;
    }
    __syncthreads();

    for (int i = threadIdx.x; i < GRID_N * MODES; i += blockDim.x) {
        int m = i / MODES;
        int q = i % MODES;
        float sre = 0.f, sim = 0.f;
        #pragma unroll 5
        for (int n = 0; n < GRID_N; n++) {
            float v = a[m * GRID_N + n];
            sre += v * g_ct[q][n];
            sim -= v * g_st[q][n];
        }
        cre[m * MODES + q] = sre;
        cim[m * MODES + q] = sim;
    }
    __syncthreads();

    for (int i = threadIdx.x; i < MODES * MODES; i += blockDim.x) {
        int p = i / MODES;
        int q = i % MODES;
        float s = 0.f;
        #pragma unroll 5
        for (int m = 0; m < GRID_N; m++)
            s += g_ct[p][m] * cre[m * MODES + q] + g_st[p][m] * cim[m * MODES + q];
        g_x[b][i] = s;
    }
}

// ---------------- driver -----------------------------------------------------
extern "C" void kernel_launch(void* const* d_in, const int* in_sizes, int n_in,
                              void* d_out, int out_size)
{
    const float* x     = (const float*)d_in[0];
    const float* W_ih  = (const float*)d_in[1];
    const float* W_hh  = (const float*)d_in[2];
    const float* b_ih  = (const float*)d_in[3];
    const float* b_hh  = (const float*)d_in[4];
    const float* fc_w  = (const float*)d_in[5];
    const float* fc_b  = (const float*)d_in[6];
    float*       out   = (float*)d_out;

    init_kernel<<<64, 256>>>(x);
    repack_gru<<<592, 256>>>(W_ih, W_hh);
    repack_fc<<<128, 256>>>(fc_w);

    for (int t = 0; t < TIME; t++) {
        int src = t & 1;
        float* outp = out + (size_t)t * BATCH * OUTDIM;

        // K1: all hh mats (depend only on old h) + ih layer 0 — one fat launch
        gru_gemm<<<dim3(48, 8, 4), 128>>>(src, 0, 3, 4, 5);
        gru_cell<<<128, 256>>>(0, src, b_ih, b_hh);
        gru_gemm<<<dim3(48, 8, 1), 128>>>(src, 1, 0, 0, 0);
        gru_cell<<<128, 256>>>(1, src, b_ih, b_hh);
        gru_gemm<<<dim3(48, 8, 1), 128>>>(src, 2, 0, 0, 0);
        gru_cell<<<128, 256>>>(2, src, b_ih, b_hh);
        fc_gemm<<<dim3(40, KS_FC), 128>>>(src);
        spectral_kernel<<<BATCH, 256>>>(fc_b, outp);
    }
}